// round 15
// baseline (speedup 1.0000x reference)
#include <cuda_runtime.h>
#include <cuda_bf16.h>

// Pooled attention embedding bag, GB300 (sm_103) — HMMA tensor-core version.
//   B=8192 bags, L<=64/bag (via offsets), D=64, ATT=64, K=4.
//   out[b,k,:] = sum_i softmax_i( tanh(E_i @ Wp^T + b) @ att_h )[k] * E_i
//
// R14: 2 bags/CTA, 128 thr / 4 warps, 22.4KB smem -> 8 CTAs/SM (8 independent
//      phase chains). B operand fragments precomputed by the prep kernel by
//      RUNNING ldmatrix on a staged tile and dumping lane registers to
//      g_Bfrag (8KB, L1-resident, shared by all CTAs) -> no per-CTA B smem
//      or staging. Gather-first overlap, MLP-8 pooling, 2-warp/bag softmax.

namespace {
constexpr int Dm = 64, KN = 4, NB = 2, MAXI = 64, NT = 128;
constexpr int LDA  = 72;              // bf16 row stride (144B)
// dynamic smem offsets (bytes)
constexpr int AS_OFF  = 0;                     // bf16 As[128][72]  18432
constexpr int AT_OFF  = 18432;                 // float At[128][4]   2048
constexpr int AH_OFF  = 20480;                 // float Ah[64][4]    1024
constexpr int PB_OFF  = 21504;                 // float Pb[64]        256
constexpr int RED_OFF = 21760;                 // float red[2][4]      64
constexpr int IDX_OFF = 21824;                 // int s_idx[128]      512
constexpr int ST_OFF  = 22336;                 // ll s_start[2]        16
constexpr int CNT_OFF = 22352;                 // int s_cnt[2]          8
constexpr int SMEM_BYTES = 22400;
}

__device__ int   g_idx_is64;
__device__ uint4 g_Bfrag[16 * 32];     // [ks*4+np][lane] -> (b0,b1,b2,b3)

using ull = unsigned long long;

__device__ __forceinline__ float tanh_fast(float x) {
    float y; asm("tanh.approx.f32 %0, %1;" : "=f"(y) : "f"(x)); return y;
}
__device__ __forceinline__ void ffma2(ull& d, ull a, ull b) {
    asm("fma.rn.f32x2 %0, %1, %2, %0;" : "+l"(d) : "l"(a), "l"(b));
}
__device__ __forceinline__ ull bcast2(float x) {
    ull r; asm("mov.b64 %0, {%1, %1};" : "=l"(r) : "f"(x)); return r;
}
__device__ __forceinline__ void unpack2(float& lo, float& hi, ull v) {
    asm("mov.b64 {%0, %1}, %2;" : "=f"(lo), "=f"(hi) : "l"(v));
}
__device__ __forceinline__ long long ld_idx(const void* p, long long i, int is64) {
    return is64 ? ((const long long*)p)[i] : (long long)((const int*)p)[i];
}
__device__ __forceinline__ unsigned smem_u32(const void* p) {
    unsigned a;
    asm("{ .reg .u64 t; cvta.to.shared.u64 t, %1; cvt.u32.u64 %0, t; }"
        : "=r"(a) : "l"(p));
    return a;
}
__device__ __forceinline__ void ldsm_x4(unsigned& r0, unsigned& r1,
                                        unsigned& r2, unsigned& r3, unsigned addr) {
    asm volatile("ldmatrix.sync.aligned.m8n8.x4.shared.b16 {%0,%1,%2,%3}, [%4];"
                 : "=r"(r0), "=r"(r1), "=r"(r2), "=r"(r3) : "r"(addr));
}
__device__ __forceinline__ void mma16816(float* c, unsigned a0, unsigned a1,
                                         unsigned a2, unsigned a3,
                                         unsigned b0, unsigned b1) {
    asm volatile(
        "mma.sync.aligned.m16n8k16.row.col.f32.bf16.bf16.f32 "
        "{%0,%1,%2,%3}, {%4,%5,%6,%7}, {%8,%9}, {%0,%1,%2,%3};"
        : "+f"(c[0]), "+f"(c[1]), "+f"(c[2]), "+f"(c[3])
        : "r"(a0), "r"(a1), "r"(a2), "r"(a3), "r"(b0), "r"(b1));
}

// prep: stage projw bf16 tile in smem, run the EXACT ldmatrix loads the main
// kernel used to do, dump lane registers to g_Bfrag. Also detect index dtype.
extern "C" __global__ void prep_kernel(const float* __restrict__ projw,
                                       const void* __restrict__ input_,
                                       const void* __restrict__ offsets,
                                       long long nnz, int nseg, long long vocab) {
    __shared__ __align__(16) __nv_bfloat16 Bs[64 * LDA];
    const int t = threadIdx.x, l = t & 31;

    for (int q = t; q < 1024; q += 256) {    // 64 rows x 16 packs of 4 bf16
        const float* s = projw + q * 4;
        __nv_bfloat162 lo = __floats2bfloat162_rn(s[0], s[1]);
        __nv_bfloat162 hi = __floats2bfloat162_rn(s[2], s[3]);
        ull v = ((ull)(*reinterpret_cast<unsigned*>(&hi)) << 32)
              |  (ull)(*reinterpret_cast<unsigned*>(&lo));
        int row = q >> 4, cp = q & 15;
        *reinterpret_cast<ull*>(Bs + row * LDA + cp * 4) = v;
    }
    __syncthreads();
    if (t < 32) {                            // warp 0 generates fragments
        for (int ks = 0; ks < 4; ++ks)
            for (int np = 0; np < 4; ++np) {
                unsigned b0, b1, b2, b3;
                const __nv_bfloat16* bp =
                    Bs + (16 * np + 8 * (l >> 4) + (l & 7)) * LDA
                       + ks * 16 + ((l >> 3) & 1) * 8;
                ldsm_x4(b0, b1, b2, b3, smem_u32(bp));
                g_Bfrag[(ks * 4 + np) * 32 + l] = make_uint4(b0, b1, b2, b3);
            }
    }
    if (t == 0) {
        bool ok = true;
        const long long* o64 = (const long long*)offsets;
        int no = nseg < 4 ? nseg : 4;
        long long prev = -1;
        for (int i = 0; i < no; ++i) {
            long long v = o64[i];
            if (v < 0 || v > nnz || v < prev) ok = false;
            prev = v;
        }
        const long long* in64 = (const long long*)input_;
        long long ni = nnz < 8 ? nnz : 8;
        for (long long i = 0; i < ni; ++i) {
            long long v = in64[i];
            if (v < 0 || v >= vocab) ok = false;
        }
        g_idx_is64 = ok ? 1 : 0;
    }
}

extern "C" __global__ void __launch_bounds__(NT, 8)
pooled_att_hmma(const void*  __restrict__ input_,
                const void*  __restrict__ offsets,
                const float* __restrict__ emb,
                const float* __restrict__ projb,
                const float* __restrict__ atth,
                float*       __restrict__ out,
                int nseg, long long nnz)
{
    extern __shared__ __align__(16) char smem[];
    __nv_bfloat16* As = (__nv_bfloat16*)(smem + AS_OFF);
    float* At   = (float*)(smem + AT_OFF);
    float* Ah   = (float*)(smem + AH_OFF);
    float* Pbs  = (float*)(smem + PB_OFF);
    float* red  = (float*)(smem + RED_OFF);
    int*   s_idx  = (int*)(smem + IDX_OFF);
    long long* s_start = (long long*)(smem + ST_OFF);
    int*       s_cnt   = (int*)(smem + CNT_OFF);

    const int tid = threadIdx.x;
    const int w   = tid >> 5;
    const int l   = tid & 31;
    const int is64 = g_idx_is64;

    // ---- gather FIRST (per-thread ranges; no barrier before) ----
    {
        const int half = tid & 1;
        #pragma unroll
        for (int wave = 0; wave < 2; ++wave) {
            const int row = (tid >> 1) + wave * 64;
            const int b = row >> 6, it = row & 63;
            const int bg = blockIdx.x * NB + b;
            int cnt = 0; long long st = 0;
            if (bg < nseg) {
                st = ld_idx(offsets, bg, is64);
                long long en = (bg + 1 < nseg) ? ld_idx(offsets, bg + 1, is64) : nnz;
                long long cc = en - st;
                cnt = (int)(cc < 0 ? 0 : (cc > MAXI ? MAXI : cc));
            }
            const bool valid = it < cnt;
            long long idx = 0;
            if (valid) idx = ld_idx(input_, st + it, is64);
            if (half == 0) s_idx[row] = (int)idx;
            if (half == 0 && it == 0) { s_cnt[b] = cnt; s_start[b] = st; }
            const float4* src =
                reinterpret_cast<const float4*>(emb + idx * (long long)Dm + half * 32);
            __nv_bfloat16* dst = As + row * LDA + half * 32;
            #pragma unroll
            for (int c = 0; c < 8; ++c) {
                float4 v = make_float4(0.f, 0.f, 0.f, 0.f);
                if (valid) v = src[c];
                __nv_bfloat162 lo = __floats2bfloat162_rn(v.x, v.y);
                __nv_bfloat162 hi = __floats2bfloat162_rn(v.z, v.w);
                ull pv = ((ull)(*reinterpret_cast<unsigned*>(&hi)) << 32)
                       |  (ull)(*reinterpret_cast<unsigned*>(&lo));
                *reinterpret_cast<ull*>(dst + c * 4) = pv;
            }
        }
    }
    // ---- stage Ah, Pb (overlaps gather latency) ----
    if (tid < 64) Pbs[tid] = projb[tid];
    #pragma unroll
    for (int q = tid; q < 256; q += NT) Ah[q] = atth[q];
    __syncthreads();                       // As + s_cnt ready

    // ---- HMMA GEMM in 2 m-passes (warp w: rows pass*64 + 16w ..+15) ----
    for (int pass = 0; pass < 2; ++pass) {
        const int rbase = pass * 64 + 16 * w;

        float acc[8][4];
        #pragma unroll
        for (int n = 0; n < 8; ++n)
            #pragma unroll
            for (int j = 0; j < 4; ++j) acc[n][j] = 0.f;

        #pragma unroll
        for (int ks = 0; ks < 4; ++ks) {
            unsigned a0, a1, a2, a3;
            {
                const __nv_bfloat16* ap =
                    As + (rbase + (l & 15)) * LDA + ks * 16 + (l >> 4) * 8;
                ldsm_x4(a0, a1, a2, a3, smem_u32(ap));
            }
            #pragma unroll
            for (int np = 0; np < 4; ++np) {
                uint4 bf = __ldg(&g_Bfrag[(ks * 4 + np) * 32 + l]);
                mma16816(acc[2 * np],     a0, a1, a2, a3, bf.x, bf.y);
                mma16816(acc[2 * np + 1], a0, a1, a2, a3, bf.z, bf.w);
            }
        }

        // epilogue: tanh+bias, x att_h, quad reduce -> At
        const int grp = l >> 2, qd = l & 3;
        float pA0 = 0.f, pA1 = 0.f, pA2 = 0.f, pA3 = 0.f;
        float pB0 = 0.f, pB1 = 0.f, pB2 = 0.f, pB3 = 0.f;
        #pragma unroll
        for (int n = 0; n < 8; ++n) {
            #pragma unroll
            for (int j = 0; j < 2; ++j) {
                const int col = 8 * n + 2 * qd + j;
                const float bias = Pbs[col];
                float hA = tanh_fast(acc[n][j] + bias);
                float hB = tanh_fast(acc[n][2 + j] + bias);
                float4 av = *reinterpret_cast<const float4*>(Ah + col * 4);
                pA0 += hA * av.x; pA1 += hA * av.y; pA2 += hA * av.z; pA3 += hA * av.w;
                pB0 += hB * av.x; pB1 += hB * av.y; pB2 += hB * av.z; pB3 += hB * av.w;
            }
        }
        #pragma unroll
        for (int off = 1; off <= 2; off <<= 1) {
            pA0 += __shfl_xor_sync(0xffffffffu, pA0, off);
            pA1 += __shfl_xor_sync(0xffffffffu, pA1, off);
            pA2 += __shfl_xor_sync(0xffffffffu, pA2, off);
            pA3 += __shfl_xor_sync(0xffffffffu, pA3, off);
            pB0 += __shfl_xor_sync(0xffffffffu, pB0, off);
            pB1 += __shfl_xor_sync(0xffffffffu, pB1, off);
            pB2 += __shfl_xor_sync(0xffffffffu, pB2, off);
            pB3 += __shfl_xor_sync(0xffffffffu, pB3, off);
        }
        if (qd == 0) {
            const int rA = rbase + grp;
            *reinterpret_cast<float4*>(At + rA * 4) =
                make_float4(pA0, pA1, pA2, pA3);
            *reinterpret_cast<float4*>(At + (rA + 8) * 4) =
                make_float4(pB0, pB1, pB2, pB3);
        }
    }
    __syncthreads();                       // At ready

    // ---- ragged softmax: 2 warps per bag (all 4 warps active) ----
    {
        const int bagw = w >> 1;            // 0..1
        const int k    = (w & 1) * 2 + (l & 1);
        const int grp  = l >> 1;            // 0..15
        const int c = s_cnt[bagw];
        float* ab = At + (bagw * MAXI) * KN + k;
        float m = -1e30f;
        #pragma unroll
        for (int it = 0; it < 4; ++it) {
            int i = grp + (it << 4);
            if (i < c) m = fmaxf(m, ab[i * KN]);
        }
        #pragma unroll
        for (int off = 2; off <= 16; off <<= 1)
            m = fmaxf(m, __shfl_xor_sync(0xffffffffu, m, off));
        float s = 0.f;
        #pragma unroll
        for (int it = 0; it < 4; ++it) {
            int i = grp + (it << 4);
            if (i < c) {
                float e = __expf(ab[i * KN] - m);
                ab[i * KN] = e;
                s += e;
            }
        }
        #pragma unroll
        for (int off = 2; off <= 16; off <<= 1)
            s += __shfl_xor_sync(0xffffffffu, s, off);
        if (grp == 0) red[bagw * KN + k] = (s > 0.f) ? 1.0f / s : 0.f;
    }
    __syncthreads();                       // weights + red ready

    // ---- pooling: 128 threads = 2 bags x 64 d; unroll 8 (MLP 8) ----
    {
        const int b = tid >> 6, d = tid & 63;
        const int bg = blockIdx.x * NB + b;
        if (bg < nseg) {
            const int c = s_cnt[b];
            const int* sx = s_idx + b * MAXI;
            const float* ap = At + (b * MAXI) * KN;
            ull a01 = 0ull, a23 = 0ull;
            int i = 0;
            for (; i + 8 <= c; i += 8) {
                float e[8];
                #pragma unroll
                for (int t = 0; t < 8; ++t)
                    e[t] = __ldg(emb + (long long)sx[i + t] * Dm + d);
                #pragma unroll
                for (int t = 0; t < 8; ++t) {
                    double2 wv = *reinterpret_cast<const double2*>(ap + (i + t) * KN);
                    ull eb = bcast2(e[t]);
                    ffma2(a01, eb, __double_as_longlong(wv.x));
                    ffma2(a23, eb, __double_as_longlong(wv.y));
                }
            }
            for (; i < c; ++i) {
                float e = __ldg(emb + (long long)sx[i] * Dm + d);
                double2 wv = *reinterpret_cast<const double2*>(ap + i * KN);
                ull eb = bcast2(e);
                ffma2(a01, eb, __double_as_longlong(wv.x));
                ffma2(a23, eb, __double_as_longlong(wv.y));
            }
            float r0, r1, r2, r3;
            unpack2(r0, r1, a01);
            unpack2(r2, r3, a23);
            float* op = out + (size_t)bg * (KN * Dm) + d;
            op[0]      = r0 * red[b * KN + 0];
            op[Dm]     = r1 * red[b * KN + 1];
            op[2 * Dm] = r2 * red[b * KN + 2];
            op[3 * Dm] = r3 * red[b * KN + 3];
        }
    }
}

extern "C" void kernel_launch(void* const* d_in, const int* in_sizes, int n_in,
                              void* d_out, int out_size) {
    const void*  input_  = d_in[0];
    const void*  offsets = d_in[1];
    const float* emb     = (const float*)d_in[2];
    const float* projw   = (const float*)d_in[3];
    const float* projb   = (const float*)d_in[4];
    const float* atth    = (const float*)d_in[5];
    float* out = (float*)d_out;

    const int       nseg  = in_sizes[1];
    const long long nnz   = in_sizes[0];
    const long long vocab = (long long)in_sizes[2] / Dm;

    prep_kernel<<<1, 256>>>(projw, input_, offsets, nnz, nseg, vocab);

    cudaFuncSetAttribute(pooled_att_hmma,
                         cudaFuncAttributeMaxDynamicSharedMemorySize, SMEM_BYTES);
    const int grid = (nseg + NB - 1) / NB;
    pooled_att_hmma<<<grid, NT, SMEM_BYTES>>>(input_, offsets, emb, projb,
                                              atth, out, nseg, nnz);
}

// round 16
// speedup vs baseline: 1.5514x; 1.5514x over previous
#include <cuda_runtime.h>
#include <cuda_bf16.h>

// Pooled attention embedding bag, GB300 (sm_103) — HMMA tensor-core version.
//   B=8192 bags, L<=64/bag (via offsets), D=64, ATT=64, K=4.
//   out[b,k,:] = sum_i softmax_i( tanh(E_i @ Wp^T + b) @ att_h )[k] * E_i
//
// R15 (= R13 + coalesced gather):
//  * 4 bags/CTA, 256 thr, 8 warps, 2 HMMA m-passes, 4 CTAs/SM.
//  * Gather: 16 threads per item row (one float4 each) -> each LDG.128
//    warp-instruction covers 2 rows x 256B contiguous = 4 L1 wavefronts
//    (was ~16-32 with the 2-thread/row layout). Offsets read once per bag.
//  * B operand via ldmatrix.x4 (two n-tiles per load), smem Bs staged from
//    prepacked g_Wb (stride fix cp*4 retained).
//  * Pooling unrolled x8 (MLP 8); softmax 2 warps per bag.

namespace {
constexpr int Dm = 64, KN = 4, NB = 4, MAXI = 64, NT = 256;
constexpr int LDA  = 72;              // bf16 row stride (144B)
// dynamic smem offsets (bytes)
constexpr int AS_OFF  = 0;                     // bf16 As[256][72]  36864
constexpr int BS_OFF  = 36864;                 // bf16 Bs[64][72]    9216
constexpr int AT_OFF  = 46080;                 // float At[256][4]   4096
constexpr int AH_OFF  = 50176;                 // float Ah[64][4]    1024
constexpr int PB_OFF  = 51200;                 // float Pb[64]        256
constexpr int RED_OFF = 51456;                 // float red[4][4]      64
constexpr int IDX_OFF = 51520;                 // int s_idx[256]     1024
constexpr int ST_OFF  = 52544;                 // ll s_start[4]        32
constexpr int CNT_OFF = 52576;                 // int s_cnt[4]         16
constexpr int SMEM_BYTES = 52608;
}

__device__ int                g_idx_is64;
__device__ unsigned long long g_Wb[1024];  // projw bf16, row-major, 8B packs

using ull = unsigned long long;

__device__ __forceinline__ float tanh_fast(float x) {
    float y; asm("tanh.approx.f32 %0, %1;" : "=f"(y) : "f"(x)); return y;
}
__device__ __forceinline__ void ffma2(ull& d, ull a, ull b) {
    asm("fma.rn.f32x2 %0, %1, %2, %0;" : "+l"(d) : "l"(a), "l"(b));
}
__device__ __forceinline__ ull bcast2(float x) {
    ull r; asm("mov.b64 %0, {%1, %1};" : "=l"(r) : "f"(x)); return r;
}
__device__ __forceinline__ void unpack2(float& lo, float& hi, ull v) {
    asm("mov.b64 {%0, %1}, %2;" : "=f"(lo), "=f"(hi) : "l"(v));
}
__device__ __forceinline__ long long ld_idx(const void* p, long long i, int is64) {
    return is64 ? ((const long long*)p)[i] : (long long)((const int*)p)[i];
}
__device__ __forceinline__ unsigned smem_u32(const void* p) {
    unsigned a;
    asm("{ .reg .u64 t; cvta.to.shared.u64 t, %1; cvt.u32.u64 %0, t; }"
        : "=r"(a) : "l"(p));
    return a;
}
__device__ __forceinline__ void ldsm_x4(unsigned& r0, unsigned& r1,
                                        unsigned& r2, unsigned& r3, unsigned addr) {
    asm volatile("ldmatrix.sync.aligned.m8n8.x4.shared.b16 {%0,%1,%2,%3}, [%4];"
                 : "=r"(r0), "=r"(r1), "=r"(r2), "=r"(r3) : "r"(addr));
}
__device__ __forceinline__ void mma16816(float* c, unsigned a0, unsigned a1,
                                         unsigned a2, unsigned a3,
                                         unsigned b0, unsigned b1) {
    asm volatile(
        "mma.sync.aligned.m16n8k16.row.col.f32.bf16.bf16.f32 "
        "{%0,%1,%2,%3}, {%4,%5,%6,%7}, {%8,%9}, {%0,%1,%2,%3};"
        : "+f"(c[0]), "+f"(c[1]), "+f"(c[2]), "+f"(c[3])
        : "r"(a0), "r"(a1), "r"(a2), "r"(a3), "r"(b0), "r"(b1));
}

// prep: projw fp32 -> bf16 packed 8B (row-major); index dtype detect.
extern "C" __global__ void prep_kernel(const float* __restrict__ projw,
                                       const void* __restrict__ input_,
                                       const void* __restrict__ offsets,
                                       long long nnz, int nseg, long long vocab) {
    int t = threadIdx.x;
    for (int q = t; q < 1024; q += 256) {
        const float* s = projw + q * 4;
        __nv_bfloat162 lo = __floats2bfloat162_rn(s[0], s[1]);
        __nv_bfloat162 hi = __floats2bfloat162_rn(s[2], s[3]);
        g_Wb[q] = ((ull)(*reinterpret_cast<unsigned*>(&hi)) << 32)
                |  (ull)(*reinterpret_cast<unsigned*>(&lo));
    }
    if (t == 0) {
        bool ok = true;
        const long long* o64 = (const long long*)offsets;
        int no = nseg < 4 ? nseg : 4;
        long long prev = -1;
        for (int i = 0; i < no; ++i) {
            long long v = o64[i];
            if (v < 0 || v > nnz || v < prev) ok = false;
            prev = v;
        }
        const long long* in64 = (const long long*)input_;
        long long ni = nnz < 8 ? nnz : 8;
        for (long long i = 0; i < ni; ++i) {
            long long v = in64[i];
            if (v < 0 || v >= vocab) ok = false;
        }
        g_idx_is64 = ok ? 1 : 0;
    }
}

extern "C" __global__ void __launch_bounds__(NT, 4)
pooled_att_hmma(const void*  __restrict__ input_,
                const void*  __restrict__ offsets,
                const float* __restrict__ emb,
                const float* __restrict__ projb,
                const float* __restrict__ atth,
                float*       __restrict__ out,
                int nseg, long long nnz)
{
    extern __shared__ __align__(16) char smem[];
    __nv_bfloat16* As   = (__nv_bfloat16*)(smem + AS_OFF);
    __nv_bfloat16* Bs   = (__nv_bfloat16*)(smem + BS_OFF);
    float* At   = (float*)(smem + AT_OFF);
    float* Ah   = (float*)(smem + AH_OFF);
    float* Pbs  = (float*)(smem + PB_OFF);
    float* red  = (float*)(smem + RED_OFF);
    int*   s_idx  = (int*)(smem + IDX_OFF);
    long long* s_start = (long long*)(smem + ST_OFF);
    int*       s_cnt   = (int*)(smem + CNT_OFF);

    const int tid = threadIdx.x;
    const int w   = tid >> 5;
    const int l   = tid & 31;
    const int is64 = g_idx_is64;

    // ---- gather FIRST: 16 threads/row, one float4 each (coalesced) ----
    {
        const int c4 = tid & 15;              // float4 slot within row
        const int rsub = tid >> 4;            // 0..15: row within 16-row wave
        #pragma unroll
        for (int b = 0; b < NB; ++b) {
            const int bg = blockIdx.x * NB + b;
            int cnt = 0; long long st = 0;
            if (bg < nseg) {
                st = ld_idx(offsets, bg, is64);
                long long en = (bg + 1 < nseg) ? ld_idx(offsets, bg + 1, is64) : nnz;
                long long cc = en - st;
                cnt = (int)(cc < 0 ? 0 : (cc > MAXI ? MAXI : cc));
            }
            #pragma unroll
            for (int sub = 0; sub < 4; ++sub) {
                const int it  = sub * 16 + rsub;   // 0..63
                const int row = b * MAXI + it;
                const bool valid = it < cnt;
                long long idx = 0;
                if (valid) idx = ld_idx(input_, st + it, is64);
                if (c4 == 0) {
                    s_idx[row] = (int)idx;
                    if (it == 0) { s_cnt[b] = cnt; s_start[b] = st; }
                }
                float4 v = make_float4(0.f, 0.f, 0.f, 0.f);
                if (valid)
                    v = reinterpret_cast<const float4*>(emb + idx * (long long)Dm)[c4];
                __nv_bfloat162 lo = __floats2bfloat162_rn(v.x, v.y);
                __nv_bfloat162 hi = __floats2bfloat162_rn(v.z, v.w);
                ull pv = ((ull)(*reinterpret_cast<unsigned*>(&hi)) << 32)
                       |  (ull)(*reinterpret_cast<unsigned*>(&lo));
                *reinterpret_cast<ull*>(As + row * LDA + c4 * 4) = pv;
            }
        }
    }
    // ---- stage B (8B packs -> element offset cp*4), Ah, Pb ----
    for (int q = tid; q < 1024; q += NT) {
        int row = q >> 4, cp = q & 15;
        *reinterpret_cast<ull*>(Bs + row * LDA + cp * 4) = g_Wb[q];
    }
    if (tid < 64) Pbs[tid] = projb[tid];
    Ah[tid] = atth[tid];
    __syncthreads();                       // As + Bs + s_cnt ready

    // ---- HMMA GEMM in 2 m-passes; epilogue inside pass ----
    for (int pass = 0; pass < 2; ++pass) {
        const int rbase = pass * 128 + 16 * w;

        float acc[8][4];
        #pragma unroll
        for (int n = 0; n < 8; ++n)
            #pragma unroll
            for (int j = 0; j < 4; ++j) acc[n][j] = 0.f;

        #pragma unroll
        for (int ks = 0; ks < 4; ++ks) {
            unsigned a0, a1, a2, a3;
            {
                const __nv_bfloat16* ap =
                    As + (rbase + (l & 15)) * LDA + ks * 16 + (l >> 4) * 8;
                ldsm_x4(a0, a1, a2, a3, smem_u32(ap));
            }
            #pragma unroll
            for (int np = 0; np < 4; ++np) {   // n-tile pairs (2np, 2np+1)
                unsigned b0, b1, b2, b3;
                const __nv_bfloat16* bp =
                    Bs + (16 * np + 8 * (l >> 4) + (l & 7)) * LDA
                       + ks * 16 + ((l >> 3) & 1) * 8;
                ldsm_x4(b0, b1, b2, b3, smem_u32(bp));
                mma16816(acc[2 * np],     a0, a1, a2, a3, b0, b1);
                mma16816(acc[2 * np + 1], a0, a1, a2, a3, b2, b3);
            }
        }

        // epilogue: tanh+bias, x att_h, quad reduce -> At
        const int grp = l >> 2, qd = l & 3;
        float pA0 = 0.f, pA1 = 0.f, pA2 = 0.f, pA3 = 0.f;
        float pB0 = 0.f, pB1 = 0.f, pB2 = 0.f, pB3 = 0.f;
        #pragma unroll
        for (int n = 0; n < 8; ++n) {
            #pragma unroll
            for (int j = 0; j < 2; ++j) {
                const int col = 8 * n + 2 * qd + j;
                const float bias = Pbs[col];
                float hA = tanh_fast(acc[n][j] + bias);
                float hB = tanh_fast(acc[n][2 + j] + bias);
                float4 av = *reinterpret_cast<const float4*>(Ah + col * 4);
                pA0 += hA * av.x; pA1 += hA * av.y; pA2 += hA * av.z; pA3 += hA * av.w;
                pB0 += hB * av.x; pB1 += hB * av.y; pB2 += hB * av.z; pB3 += hB * av.w;
            }
        }
        #pragma unroll
        for (int off = 1; off <= 2; off <<= 1) {
            pA0 += __shfl_xor_sync(0xffffffffu, pA0, off);
            pA1 += __shfl_xor_sync(0xffffffffu, pA1, off);
            pA2 += __shfl_xor_sync(0xffffffffu, pA2, off);
            pA3 += __shfl_xor_sync(0xffffffffu, pA3, off);
            pB0 += __shfl_xor_sync(0xffffffffu, pB0, off);
            pB1 += __shfl_xor_sync(0xffffffffu, pB1, off);
            pB2 += __shfl_xor_sync(0xffffffffu, pB2, off);
            pB3 += __shfl_xor_sync(0xffffffffu, pB3, off);
        }
        if (qd == 0) {
            const int rA = rbase + grp;
            *reinterpret_cast<float4*>(At + rA * 4) =
                make_float4(pA0, pA1, pA2, pA3);
            *reinterpret_cast<float4*>(At + (rA + 8) * 4) =
                make_float4(pB0, pB1, pB2, pB3);
        }
    }
    __syncthreads();                       // At ready

    // ---- ragged softmax: 2 warps per bag (all 8 warps active) ----
    {
        const int bagw = w >> 1;            // 0..3
        const int k    = (w & 1) * 2 + (l & 1);
        const int grp  = l >> 1;            // 0..15
        const int c = s_cnt[bagw];
        float* ab = At + (bagw * MAXI) * KN + k;
        float m = -1e30f;
        #pragma unroll
        for (int it = 0; it < 4; ++it) {
            int i = grp + (it << 4);
            if (i < c) m = fmaxf(m, ab[i * KN]);
        }
        #pragma unroll
        for (int off = 2; off <= 16; off <<= 1)
            m = fmaxf(m, __shfl_xor_sync(0xffffffffu, m, off));
        float s = 0.f;
        #pragma unroll
        for (int it = 0; it < 4; ++it) {
            int i = grp + (it << 4);
            if (i < c) {
                float e = __expf(ab[i * KN] - m);
                ab[i * KN] = e;
                s += e;
            }
        }
        #pragma unroll
        for (int off = 2; off <= 16; off <<= 1)
            s += __shfl_xor_sync(0xffffffffu, s, off);
        if (grp == 0) red[bagw * KN + k] = (s > 0.f) ? 1.0f / s : 0.f;
    }
    __syncthreads();                       // weights + red ready

    // ---- pooling: 256 threads = 4 bags x 64 d; unroll 8 (MLP 8) ----
    {
        const int b = tid >> 6, d = tid & 63;
        const int bg = blockIdx.x * NB + b;
        if (bg < nseg) {
            const int c = s_cnt[b];
            const int* sx = s_idx + b * MAXI;
            const float* ap = At + (b * MAXI) * KN;
            ull a01 = 0ull, a23 = 0ull;
            int i = 0;
            for (; i + 8 <= c; i += 8) {
                float e[8];
                #pragma unroll
                for (int t = 0; t < 8; ++t)
                    e[t] = __ldg(emb + (long long)sx[i + t] * Dm + d);
                #pragma unroll
                for (int t = 0; t < 8; ++t) {
                    double2 wv = *reinterpret_cast<const double2*>(ap + (i + t) * KN);
                    ull eb = bcast2(e[t]);
                    ffma2(a01, eb, __double_as_longlong(wv.x));
                    ffma2(a23, eb, __double_as_longlong(wv.y));
                }
            }
            for (; i < c; ++i) {
                float e = __ldg(emb + (long long)sx[i] * Dm + d);
                double2 wv = *reinterpret_cast<const double2*>(ap + i * KN);
                ull eb = bcast2(e);
                ffma2(a01, eb, __double_as_longlong(wv.x));
                ffma2(a23, eb, __double_as_longlong(wv.y));
            }
            float r0, r1, r2, r3;
            unpack2(r0, r1, a01);
            unpack2(r2, r3, a23);
            float* op = out + (size_t)bg * (KN * Dm) + d;
            op[0]      = r0 * red[b * KN + 0];
            op[Dm]     = r1 * red[b * KN + 1];
            op[2 * Dm] = r2 * red[b * KN + 2];
            op[3 * Dm] = r3 * red[b * KN + 3];
        }
    }
}

extern "C" void kernel_launch(void* const* d_in, const int* in_sizes, int n_in,
                              void* d_out, int out_size) {
    const void*  input_  = d_in[0];
    const void*  offsets = d_in[1];
    const float* emb     = (const float*)d_in[2];
    const float* projw   = (const float*)d_in[3];
    const float* projb   = (const float*)d_in[4];
    const float* atth    = (const float*)d_in[5];
    float* out = (float*)d_out;

    const int       nseg  = in_sizes[1];
    const long long nnz   = in_sizes[0];
    const long long vocab = (long long)in_sizes[2] / Dm;

    prep_kernel<<<1, 256>>>(projw, input_, offsets, nnz, nseg, vocab);

    cudaFuncSetAttribute(pooled_att_hmma,
                         cudaFuncAttributeMaxDynamicSharedMemorySize, SMEM_BYTES);
    const int grid = (nseg + NB - 1) / NB;
    pooled_att_hmma<<<grid, NT, SMEM_BYTES>>>(input_, offsets, emb, projb,
                                              atth, out, nseg, nnz);
}

// round 17
// speedup vs baseline: 1.5812x; 1.0192x over previous
#include <cuda_runtime.h>
#include <cuda_bf16.h>

// Pooled attention embedding bag, GB300 (sm_103) — HMMA tensor-core version.
//   B=8192 bags, L<=64/bag (via offsets), D=64, ATT=64, K=4.
//   out[b,k,:] = sum_i softmax_i( tanh(E_i @ Wp^T + b) @ att_h )[k] * E_i
//
// R16 (= R15 with the prep kernel folded in -> ONE kernel, no serial launch):
//  * 4 bags/CTA, 256 thr, 8 warps, 2 HMMA m-passes, 4 CTAs/SM.
//  * Index dtype (int32 vs int64) detected inline per-thread (12 broadcast
//    loads, deterministic), overlapped with the gather.
//  * Gather: 16 threads per item row (one float4 each) — 4 L1 wavefronts per
//    LDG.128 warp-instruction; offsets read once per bag.
//  * B tile staged directly from projw with inline fp32->bf16 conversion
//    (L2-resident, coalesced; cp*4 element layout as before).
//  * B operand via ldmatrix.x4 (two n-tiles per load).
//  * Pooling unrolled x8 (MLP 8); softmax 2 warps per bag.

namespace {
constexpr int Dm = 64, KN = 4, NB = 4, MAXI = 64, NT = 256;
constexpr int LDA  = 72;              // bf16 row stride (144B)
// dynamic smem offsets (bytes)
constexpr int AS_OFF  = 0;                     // bf16 As[256][72]  36864
constexpr int BS_OFF  = 36864;                 // bf16 Bs[64][72]    9216
constexpr int AT_OFF  = 46080;                 // float At[256][4]   4096
constexpr int AH_OFF  = 50176;                 // float Ah[64][4]    1024
constexpr int PB_OFF  = 51200;                 // float Pb[64]        256
constexpr int RED_OFF = 51456;                 // float red[4][4]      64
constexpr int IDX_OFF = 51520;                 // int s_idx[256]     1024
constexpr int ST_OFF  = 52544;                 // ll s_start[4]        32
constexpr int CNT_OFF = 52576;                 // int s_cnt[4]         16
constexpr int SMEM_BYTES = 52608;
}

using ull = unsigned long long;

__device__ __forceinline__ float tanh_fast(float x) {
    float y; asm("tanh.approx.f32 %0, %1;" : "=f"(y) : "f"(x)); return y;
}
__device__ __forceinline__ void ffma2(ull& d, ull a, ull b) {
    asm("fma.rn.f32x2 %0, %1, %2, %0;" : "+l"(d) : "l"(a), "l"(b));
}
__device__ __forceinline__ ull bcast2(float x) {
    ull r; asm("mov.b64 %0, {%1, %1};" : "=l"(r) : "f"(x)); return r;
}
__device__ __forceinline__ void unpack2(float& lo, float& hi, ull v) {
    asm("mov.b64 {%0, %1}, %2;" : "=f"(lo), "=f"(hi) : "l"(v));
}
__device__ __forceinline__ long long ld_idx(const void* p, long long i, int is64) {
    return is64 ? ((const long long*)p)[i] : (long long)((const int*)p)[i];
}
__device__ __forceinline__ unsigned smem_u32(const void* p) {
    unsigned a;
    asm("{ .reg .u64 t; cvta.to.shared.u64 t, %1; cvt.u32.u64 %0, t; }"
        : "=r"(a) : "l"(p));
    return a;
}
__device__ __forceinline__ void ldsm_x4(unsigned& r0, unsigned& r1,
                                        unsigned& r2, unsigned& r3, unsigned addr) {
    asm volatile("ldmatrix.sync.aligned.m8n8.x4.shared.b16 {%0,%1,%2,%3}, [%4];"
                 : "=r"(r0), "=r"(r1), "=r"(r2), "=r"(r3) : "r"(addr));
}
__device__ __forceinline__ void mma16816(float* c, unsigned a0, unsigned a1,
                                         unsigned a2, unsigned a3,
                                         unsigned b0, unsigned b1) {
    asm volatile(
        "mma.sync.aligned.m16n8k16.row.col.f32.bf16.bf16.f32 "
        "{%0,%1,%2,%3}, {%4,%5,%6,%7}, {%8,%9}, {%0,%1,%2,%3};"
        : "+f"(c[0]), "+f"(c[1]), "+f"(c[2]), "+f"(c[3])
        : "r"(a0), "r"(a1), "r"(a2), "r"(a3), "r"(b0), "r"(b1));
}

// Inline index-dtype detection: int32 data read as int64 fails range /
// monotonicity checks deterministically. Reads <=32B of offsets, <=64B of
// input_ (broadcast L2 hits; safe for either dtype).
__device__ __forceinline__ int detect_is64(const void* input_, const void* offsets,
                                           long long nnz, int nseg, long long vocab) {
    bool ok = true;
    const long long* o64 = (const long long*)offsets;
    int no = nseg < 4 ? nseg : 4;
    long long prev = -1;
    #pragma unroll
    for (int i = 0; i < 4; ++i) {
        if (i < no) {
            long long v = o64[i];
            if (v < 0 || v > nnz || v < prev) ok = false;
            prev = v;
        }
    }
    const long long* in64 = (const long long*)input_;
    long long ni = nnz < 8 ? nnz : 8;
    #pragma unroll
    for (int i = 0; i < 8; ++i) {
        if (i < ni) {
            long long v = in64[i];
            if (v < 0 || v >= vocab) ok = false;
        }
    }
    return ok ? 1 : 0;
}

extern "C" __global__ void __launch_bounds__(NT, 4)
pooled_att_hmma(const void*  __restrict__ input_,
                const void*  __restrict__ offsets,
                const float* __restrict__ emb,
                const float* __restrict__ projw,
                const float* __restrict__ projb,
                const float* __restrict__ atth,
                float*       __restrict__ out,
                int nseg, long long nnz, long long vocab)
{
    extern __shared__ __align__(16) char smem[];
    __nv_bfloat16* As   = (__nv_bfloat16*)(smem + AS_OFF);
    __nv_bfloat16* Bs   = (__nv_bfloat16*)(smem + BS_OFF);
    float* At   = (float*)(smem + AT_OFF);
    float* Ah   = (float*)(smem + AH_OFF);
    float* Pbs  = (float*)(smem + PB_OFF);
    float* red  = (float*)(smem + RED_OFF);
    int*   s_idx  = (int*)(smem + IDX_OFF);
    long long* s_start = (long long*)(smem + ST_OFF);
    int*       s_cnt   = (int*)(smem + CNT_OFF);

    const int tid = threadIdx.x;
    const int w   = tid >> 5;
    const int l   = tid & 31;

    // ---- inline dtype detection (broadcast loads, overlaps with gather) ----
    const int is64 = detect_is64(input_, offsets, nnz, nseg, vocab);

    // ---- gather FIRST: 16 threads/row, one float4 each (coalesced) ----
    {
        const int c4 = tid & 15;              // float4 slot within row
        const int rsub = tid >> 4;            // 0..15: row within 16-row wave
        #pragma unroll
        for (int b = 0; b < NB; ++b) {
            const int bg = blockIdx.x * NB + b;
            int cnt = 0; long long st = 0;
            if (bg < nseg) {
                st = ld_idx(offsets, bg, is64);
                long long en = (bg + 1 < nseg) ? ld_idx(offsets, bg + 1, is64) : nnz;
                long long cc = en - st;
                cnt = (int)(cc < 0 ? 0 : (cc > MAXI ? MAXI : cc));
            }
            #pragma unroll
            for (int sub = 0; sub < 4; ++sub) {
                const int it  = sub * 16 + rsub;   // 0..63
                const int row = b * MAXI + it;
                const bool valid = it < cnt;
                long long idx = 0;
                if (valid) idx = ld_idx(input_, st + it, is64);
                if (c4 == 0) {
                    s_idx[row] = (int)idx;
                    if (it == 0) { s_cnt[b] = cnt; s_start[b] = st; }
                }
                float4 v = make_float4(0.f, 0.f, 0.f, 0.f);
                if (valid)
                    v = reinterpret_cast<const float4*>(emb + idx * (long long)Dm)[c4];
                __nv_bfloat162 lo = __floats2bfloat162_rn(v.x, v.y);
                __nv_bfloat162 hi = __floats2bfloat162_rn(v.z, v.w);
                ull pv = ((ull)(*reinterpret_cast<unsigned*>(&hi)) << 32)
                       |  (ull)(*reinterpret_cast<unsigned*>(&lo));
                *reinterpret_cast<ull*>(As + row * LDA + c4 * 4) = pv;
            }
        }
    }
    // ---- stage B from projw (fp32 -> bf16 inline; cp*4 layout), Ah, Pb ----
    for (int q = tid; q < 1024; q += NT) {
        int row = q >> 4, cp = q & 15;
        float4 s = reinterpret_cast<const float4*>(projw)[q];
        __nv_bfloat162 lo = __floats2bfloat162_rn(s.x, s.y);
        __nv_bfloat162 hi = __floats2bfloat162_rn(s.z, s.w);
        ull v = ((ull)(*reinterpret_cast<unsigned*>(&hi)) << 32)
              |  (ull)(*reinterpret_cast<unsigned*>(&lo));
        *reinterpret_cast<ull*>(Bs + row * LDA + cp * 4) = v;
    }
    if (tid < 64) Pbs[tid] = projb[tid];
    Ah[tid] = atth[tid];
    __syncthreads();                       // As + Bs + s_cnt ready

    // ---- HMMA GEMM in 2 m-passes; epilogue inside pass ----
    for (int pass = 0; pass < 2; ++pass) {
        const int rbase = pass * 128 + 16 * w;

        float acc[8][4];
        #pragma unroll
        for (int n = 0; n < 8; ++n)
            #pragma unroll
            for (int j = 0; j < 4; ++j) acc[n][j] = 0.f;

        #pragma unroll
        for (int ks = 0; ks < 4; ++ks) {
            unsigned a0, a1, a2, a3;
            {
                const __nv_bfloat16* ap =
                    As + (rbase + (l & 15)) * LDA + ks * 16 + (l >> 4) * 8;
                ldsm_x4(a0, a1, a2, a3, smem_u32(ap));
            }
            #pragma unroll
            for (int np = 0; np < 4; ++np) {   // n-tile pairs (2np, 2np+1)
                unsigned b0, b1, b2, b3;
                const __nv_bfloat16* bp =
                    Bs + (16 * np + 8 * (l >> 4) + (l & 7)) * LDA
                       + ks * 16 + ((l >> 3) & 1) * 8;
                ldsm_x4(b0, b1, b2, b3, smem_u32(bp));
                mma16816(acc[2 * np],     a0, a1, a2, a3, b0, b1);
                mma16816(acc[2 * np + 1], a0, a1, a2, a3, b2, b3);
            }
        }

        // epilogue: tanh+bias, x att_h, quad reduce -> At
        const int grp = l >> 2, qd = l & 3;
        float pA0 = 0.f, pA1 = 0.f, pA2 = 0.f, pA3 = 0.f;
        float pB0 = 0.f, pB1 = 0.f, pB2 = 0.f, pB3 = 0.f;
        #pragma unroll
        for (int n = 0; n < 8; ++n) {
            #pragma unroll
            for (int j = 0; j < 2; ++j) {
                const int col = 8 * n + 2 * qd + j;
                const float bias = Pbs[col];
                float hA = tanh_fast(acc[n][j] + bias);
                float hB = tanh_fast(acc[n][2 + j] + bias);
                float4 av = *reinterpret_cast<const float4*>(Ah + col * 4);
                pA0 += hA * av.x; pA1 += hA * av.y; pA2 += hA * av.z; pA3 += hA * av.w;
                pB0 += hB * av.x; pB1 += hB * av.y; pB2 += hB * av.z; pB3 += hB * av.w;
            }
        }
        #pragma unroll
        for (int off = 1; off <= 2; off <<= 1) {
            pA0 += __shfl_xor_sync(0xffffffffu, pA0, off);
            pA1 += __shfl_xor_sync(0xffffffffu, pA1, off);
            pA2 += __shfl_xor_sync(0xffffffffu, pA2, off);
            pA3 += __shfl_xor_sync(0xffffffffu, pA3, off);
            pB0 += __shfl_xor_sync(0xffffffffu, pB0, off);
            pB1 += __shfl_xor_sync(0xffffffffu, pB1, off);
            pB2 += __shfl_xor_sync(0xffffffffu, pB2, off);
            pB3 += __shfl_xor_sync(0xffffffffu, pB3, off);
        }
        if (qd == 0) {
            const int rA = rbase + grp;
            *reinterpret_cast<float4*>(At + rA * 4) =
                make_float4(pA0, pA1, pA2, pA3);
            *reinterpret_cast<float4*>(At + (rA + 8) * 4) =
                make_float4(pB0, pB1, pB2, pB3);
        }
    }
    __syncthreads();                       // At ready

    // ---- ragged softmax: 2 warps per bag (all 8 warps active) ----
    {
        const int bagw = w >> 1;            // 0..3
        const int k    = (w & 1) * 2 + (l & 1);
        const int grp  = l >> 1;            // 0..15
        const int c = s_cnt[bagw];
        float* ab = At + (bagw * MAXI) * KN + k;
        float m = -1e30f;
        #pragma unroll
        for (int it = 0; it < 4; ++it) {
            int i = grp + (it << 4);
            if (i < c) m = fmaxf(m, ab[i * KN]);
        }
        #pragma unroll
        for (int off = 2; off <= 16; off <<= 1)
            m = fmaxf(m, __shfl_xor_sync(0xffffffffu, m, off));
        float s = 0.f;
        #pragma unroll
        for (int it = 0; it < 4; ++it) {
            int i = grp + (it << 4);
            if (i < c) {
                float e = __expf(ab[i * KN] - m);
                ab[i * KN] = e;
                s += e;
            }
        }
        #pragma unroll
        for (int off = 2; off <= 16; off <<= 1)
            s += __shfl_xor_sync(0xffffffffu, s, off);
        if (grp == 0) red[bagw * KN + k] = (s > 0.f) ? 1.0f / s : 0.f;
    }
    __syncthreads();                       // weights + red ready

    // ---- pooling: 256 threads = 4 bags x 64 d; unroll 8 (MLP 8) ----
    {
        const int b = tid >> 6, d = tid & 63;
        const int bg = blockIdx.x * NB + b;
        if (bg < nseg) {
            const int c = s_cnt[b];
            const int* sx = s_idx + b * MAXI;
            const float* ap = At + (b * MAXI) * KN;
            ull a01 = 0ull, a23 = 0ull;
            int i = 0;
            for (; i + 8 <= c; i += 8) {
                float e[8];
                #pragma unroll
                for (int t = 0; t < 8; ++t)
                    e[t] = __ldg(emb + (long long)sx[i + t] * Dm + d);
                #pragma unroll
                for (int t = 0; t < 8; ++t) {
                    double2 wv = *reinterpret_cast<const double2*>(ap + (i + t) * KN);
                    ull eb = bcast2(e[t]);
                    ffma2(a01, eb, __double_as_longlong(wv.x));
                    ffma2(a23, eb, __double_as_longlong(wv.y));
                }
            }
            for (; i < c; ++i) {
                float e = __ldg(emb + (long long)sx[i] * Dm + d);
                double2 wv = *reinterpret_cast<const double2*>(ap + i * KN);
                ull eb = bcast2(e);
                ffma2(a01, eb, __double_as_longlong(wv.x));
                ffma2(a23, eb, __double_as_longlong(wv.y));
            }
            float r0, r1, r2, r3;
            unpack2(r0, r1, a01);
            unpack2(r2, r3, a23);
            float* op = out + (size_t)bg * (KN * Dm) + d;
            op[0]      = r0 * red[b * KN + 0];
            op[Dm]     = r1 * red[b * KN + 1];
            op[2 * Dm] = r2 * red[b * KN + 2];
            op[3 * Dm] = r3 * red[b * KN + 3];
        }
    }
}

extern "C" void kernel_launch(void* const* d_in, const int* in_sizes, int n_in,
                              void* d_out, int out_size) {
    const void*  input_  = d_in[0];
    const void*  offsets = d_in[1];
    const float* emb     = (const float*)d_in[2];
    const float* projw   = (const float*)d_in[3];
    const float* projb   = (const float*)d_in[4];
    const float* atth    = (const float*)d_in[5];
    float* out = (float*)d_out;

    const int       nseg  = in_sizes[1];
    const long long nnz   = in_sizes[0];
    const long long vocab = (long long)in_sizes[2] / Dm;

    cudaFuncSetAttribute(pooled_att_hmma,
                         cudaFuncAttributeMaxDynamicSharedMemorySize, SMEM_BYTES);
    const int grid = (nseg + NB - 1) / NB;
    pooled_att_hmma<<<grid, NT, SMEM_BYTES>>>(input_, offsets, emb, projw, projb,
                                              atth, out, nseg, nnz, vocab);
}